// round 2
// baseline (speedup 1.0000x reference)
#include <cuda_runtime.h>
#include <cstdint>
#include <cstddef>

#define D_MODEL 1024
#define N_BATCH 4
#define N_SEQ   2048
#define N_HEADS 16
#define D_HEAD  64
#define N_ROWS  (N_BATCH * N_SEQ)   // 8192

// Scratch (device-global: no allocations allowed in kernel_launch).
__device__ float g_Q[(size_t)N_ROWS * D_MODEL];
__device__ float g_K[(size_t)N_ROWS * D_MODEL];
__device__ float g_V[(size_t)N_ROWS * D_MODEL];
__device__ float g_CTX[(size_t)N_ROWS * D_MODEL];

// ---------------------------------------------------------------------------
// Helpers
// ---------------------------------------------------------------------------
__device__ __forceinline__ uint32_t f2tf32(float x) {
    uint32_t r;
    asm("cvt.rna.tf32.f32 %0, %1;" : "=r"(r) : "f"(x));
    return r;
}

// D += A(16x8,row) * B(8x8,col)  tf32 -> fp32
__device__ __forceinline__ void mma_tf32(float d[4], const uint32_t a[4], const uint32_t b[2]) {
    asm volatile(
        "mma.sync.aligned.m16n8k8.row.col.f32.tf32.tf32.f32 "
        "{%0,%1,%2,%3}, {%4,%5,%6,%7}, {%8,%9}, {%0,%1,%2,%3};\n"
        : "+f"(d[0]), "+f"(d[1]), "+f"(d[2]), "+f"(d[3])
        : "r"(a[0]), "r"(a[1]), "r"(a[2]), "r"(a[3]), "r"(b[0]), "r"(b[1]));
}

__device__ __forceinline__ void cp16(uint32_t s, const void* g) {
    asm volatile("cp.async.cg.shared.global [%0], [%1], 16;\n" :: "r"(s), "l"(g));
}
__device__ __forceinline__ void cp_commit() { asm volatile("cp.async.commit_group;\n"); }
__device__ __forceinline__ void cp_wait0()  { asm volatile("cp.async.wait_group 0;\n"); }

// In-place convert a raw fp32 smem buffer to tf32 bit patterns (round-to-
// nearest), float4 vectorized. Each element converted exactly ONCE per tile
// instead of once per consuming warp -> big ALU-pipe saving.
__device__ __forceinline__ void cvt_buf(float* p, int n4, int tid, int nthr) {
    float4* p4 = (float4*)p;
    for (int i = tid; i < n4; i += nthr) {
        float4 v = p4[i];
        v.x = __uint_as_float(f2tf32(v.x));
        v.y = __uint_as_float(f2tf32(v.y));
        v.z = __uint_as_float(f2tf32(v.z));
        v.w = __uint_as_float(f2tf32(v.w));
        p4[i] = v;
    }
}

// exp(x) for x <= 0 using only FMA/ALU pipe (MUFU on sm_10x would cost ~2 ms
// for the 268M softmax exps). ~3e-6 rel accuracy.
__device__ __forceinline__ float fast_exp(float x) {
    float t = fmaxf(x * 1.4426950408889634f, -126.0f);   // log2(e)*x, clamped
    float z = t + 12582912.0f;                           // round-to-nearest int
    int  ki = __float_as_int(z) - 0x4B400000;
    float f = t - (z - 12582912.0f);                     // f in [-0.5, 0.5]
    float u = f * 0.6931471805599453f;
    float p = 1.0f + u * (1.0f + u * (0.5f + u * (0.16666667f +
              u * (0.041666668f + u * 0.008333334f))));
    return __int_as_float(__float_as_int(p) + (ki << 23));
}

// ---------------------------------------------------------------------------
// GEMM: C[8192,1024] = A[8192,1024] @ W[1024,1024] + bias
// BM=128 BN=128 BK=32, 256 threads (8 warps, 4x2), warp tile 32x64,
// tf32 m16n8k8, cp.async double-buffered, pre-converted tf32 smem.
// ---------------------------------------------------------------------------
#define BM 128
#define BN 128
#define BK 32
#define ASTR 36    // (36g+t)%32 = 4g+t -> conflict-free A-frag LDS; 144B row, 16B-aligned
#define BSTR 136   // (136t+g)%32 = 8t+g -> conflict-free B-frag LDS; 544B row, 16B-aligned
#define A_BUF (BM * ASTR)            // 4608 floats
#define B_BUF (BK * BSTR)            // 4352 floats
#define GEMM_SMEM ((2 * A_BUF + 2 * B_BUF) * 4)   // 71680 B

__global__ void __launch_bounds__(256)
gemm_bias_kernel(const float* __restrict__ A, const float* __restrict__ W,
                 const float* __restrict__ bias, float* __restrict__ C)
{
    extern __shared__ float smem[];
    float* As = smem;                     // [2][BM][ASTR]
    float* Bs = smem + 2 * A_BUF;         // [2][BK][BSTR]
    const uint32_t sA = (uint32_t)__cvta_generic_to_shared(As);
    const uint32_t sB = (uint32_t)__cvta_generic_to_shared(Bs);

    const int tid  = threadIdx.x;
    const int warp = tid >> 5, lane = tid & 31;
    const int g = lane >> 2, t = lane & 3;            // mma group / thread-in-group
    const int wm = warp >> 1, wn = warp & 1;          // 4 x 2 warps
    const int m_base = wm * 32, n_base = wn * 64;
    const int cta_m = blockIdx.y * BM;
    const int cta_n = blockIdx.x * BN;

    float acc[2][8][4];
    #pragma unroll
    for (int i = 0; i < 2; i++)
        #pragma unroll
        for (int j = 0; j < 8; j++)
            #pragma unroll
            for (int e = 0; e < 4; e++) acc[i][j][e] = 0.f;

    auto issue_loads = [&](int kt, int buf) {
        const float* Ag = A + (size_t)cta_m * D_MODEL + kt * BK;
        #pragma unroll
        for (int i = 0; i < 4; i++) {                  // A: 128x32 = 1024 float4
            int idx = tid + i * 256;
            int r = idx >> 3, c = (idx & 7) * 4;
            cp16(sA + (uint32_t)(buf * A_BUF + r * ASTR + c) * 4,
                 Ag + (size_t)r * D_MODEL + c);
        }
        const float* Wg = W + (size_t)(kt * BK) * D_MODEL + cta_n;
        #pragma unroll
        for (int i = 0; i < 4; i++) {                  // B: 32x128 = 1024 float4
            int idx = tid + i * 256;
            int r = idx >> 5, c = (idx & 31) * 4;
            cp16(sB + (uint32_t)(buf * B_BUF + r * BSTR + c) * 4,
                 Wg + (size_t)r * D_MODEL + c);
        }
        cp_commit();
    };

    issue_loads(0, 0);

    const int KT = D_MODEL / BK;  // 32
    for (int kt = 0; kt < KT; kt++) {
        cp_wait0();
        __syncthreads();                   // tile kt landed; prev compute done
        if (kt + 1 < KT) issue_loads(kt + 1, (kt + 1) & 1);   // overlaps below

        float* Ab = As + (kt & 1) * A_BUF;
        float* Bb = Bs + (kt & 1) * B_BUF;
        cvt_buf(Ab, A_BUF / 4, tid, 256);  // pads converted too: harmless
        cvt_buf(Bb, B_BUF / 4, tid, 256);
        __syncthreads();

        #pragma unroll
        for (int kk = 0; kk < 4; kk++) {
            const int k0 = kk * 8;
            uint32_t af[2][4], bf[8][2];
            #pragma unroll
            for (int mt = 0; mt < 2; mt++) {
                const int m0 = m_base + mt * 16;
                af[mt][0] = __float_as_uint(Ab[(m0 + g)     * ASTR + k0 + t]);
                af[mt][1] = __float_as_uint(Ab[(m0 + g + 8) * ASTR + k0 + t]);
                af[mt][2] = __float_as_uint(Ab[(m0 + g)     * ASTR + k0 + t + 4]);
                af[mt][3] = __float_as_uint(Ab[(m0 + g + 8) * ASTR + k0 + t + 4]);
            }
            #pragma unroll
            for (int nt = 0; nt < 8; nt++) {
                const int n0 = n_base + nt * 8;
                bf[nt][0] = __float_as_uint(Bb[(k0 + t)     * BSTR + n0 + g]);
                bf[nt][1] = __float_as_uint(Bb[(k0 + t + 4) * BSTR + n0 + g]);
            }
            #pragma unroll
            for (int mt = 0; mt < 2; mt++)
                #pragma unroll
                for (int nt = 0; nt < 8; nt++)
                    mma_tf32(acc[mt][nt], af[mt], bf[nt]);
        }
        __syncthreads();                   // done reading buf before reuse
    }

    // Epilogue: + bias, float2 stores (c0/c1 are adjacent columns)
    #pragma unroll
    for (int mt = 0; mt < 2; mt++) {
        #pragma unroll
        for (int nt = 0; nt < 8; nt++) {
            int r0 = cta_m + m_base + mt * 16 + g;
            int c0 = cta_n + n_base + nt * 8 + 2 * t;
            float b0 = bias[c0], b1 = bias[c0 + 1];
            *(float2*)(C + (size_t)r0 * D_MODEL + c0) =
                make_float2(acc[mt][nt][0] + b0, acc[mt][nt][1] + b1);
            *(float2*)(C + (size_t)(r0 + 8) * D_MODEL + c0) =
                make_float2(acc[mt][nt][2] + b0, acc[mt][nt][3] + b1);
        }
    }
}

// ---------------------------------------------------------------------------
// Flash attention: one CTA = 128 queries of one (b,h). 8 warps, each owns 16
// query rows (softmax warp-local). K/V tiles (64 kv rows) are cp.async
// double-buffered and pre-converted to tf32 once per tile (shared by all 8
// warps). Online softmax; P round-trips through smem as tf32 A-fragments.
// 1/sqrt(Dh) folded into Q fragments.
// ---------------------------------------------------------------------------
#define QTILE 128
#define KSTR 68   // (68g+t)%32 = 4g+t -> conflict-free B-frag reads of K
#define VSTR 72   // (72t+g)%32 = 8t+g -> conflict-free B-frag reads of V
#define PSTR 68
#define K_BUF (64 * KSTR)   // 4352 floats
#define V_BUF (64 * VSTR)   // 4608 floats
#define ATTN_SMEM ((2 * K_BUF + 2 * V_BUF + QTILE * PSTR) * 4)   // 106496 B

__global__ void __launch_bounds__(256)
attn_kernel()
{
    extern __shared__ float sm[];
    float* Ks = sm;                        // [2][64][KSTR]
    float* Vs = sm + 2 * K_BUF;            // [2][64][VSTR]
    float* Ps = sm + 2 * K_BUF + 2 * V_BUF; // [128][PSTR] Q staging then P
    const uint32_t sK = (uint32_t)__cvta_generic_to_shared(Ks);
    const uint32_t sV = (uint32_t)__cvta_generic_to_shared(Vs);
    const uint32_t sP = (uint32_t)__cvta_generic_to_shared(Ps);

    const int tid  = threadIdx.x;
    const int warp = tid >> 5, lane = tid & 31;
    const int g = lane >> 2, t = lane & 3;
    const int b = blockIdx.z, h = blockIdx.y;
    const int s0 = blockIdx.x * QTILE;
    const int q0 = warp * 16;                  // this warp's query rows

    // ---- stage Q tile in Ps, pull register A-fragments (pre-scaled by 1/8)
    {
        const float* Qg = g_Q + ((size_t)(b * N_SEQ + s0)) * D_MODEL + h * D_HEAD;
        #pragma unroll
        for (int i = 0; i < 8; i++) {          // 128x64 = 2048 float4
            int idx = tid + i * 256;
            int r = idx >> 4, c = (idx & 15) * 4;
            cp16(sP + (uint32_t)(r * PSTR + c) * 4, Qg + (size_t)r * D_MODEL + c);
        }
        cp_commit(); cp_wait0();
        __syncthreads();
    }
    uint32_t qf[8][4];
    #pragma unroll
    for (int kk = 0; kk < 8; kk++) {
        const int k0 = kk * 8;
        qf[kk][0] = f2tf32(Ps[(q0 + g)     * PSTR + k0 + t]     * 0.125f);
        qf[kk][1] = f2tf32(Ps[(q0 + g + 8) * PSTR + k0 + t]     * 0.125f);
        qf[kk][2] = f2tf32(Ps[(q0 + g)     * PSTR + k0 + t + 4] * 0.125f);
        qf[kk][3] = f2tf32(Ps[(q0 + g + 8) * PSTR + k0 + t + 4] * 0.125f);
    }
    __syncthreads();   // Ps now reusable as P buffer

    auto issue_kv = [&](int kt, int buf) {
        const float* Kg = g_K + ((size_t)(b * N_SEQ + kt * 64)) * D_MODEL + h * D_HEAD;
        const float* Vg = g_V + ((size_t)(b * N_SEQ + kt * 64)) * D_MODEL + h * D_HEAD;
        #pragma unroll
        for (int i = 0; i < 4; i++) {          // 64x64 = 1024 float4 each
            int idx = tid + i * 256;
            int r = idx >> 4, c = (idx & 15) * 4;
            cp16(sK + (uint32_t)(buf * K_BUF + r * KSTR + c) * 4,
                 Kg + (size_t)r * D_MODEL + c);
            cp16(sV + (uint32_t)(buf * V_BUF + r * VSTR + c) * 4,
                 Vg + (size_t)r * D_MODEL + c);
        }
        cp_commit();
    };

    float m0 = -1e30f, m1 = -1e30f, l0 = 0.f, l1 = 0.f;
    float o[8][4];
    #pragma unroll
    for (int dt = 0; dt < 8; dt++)
        #pragma unroll
        for (int e = 0; e < 4; e++) o[dt][e] = 0.f;

    issue_kv(0, 0);

    const int NT = N_SEQ / 64;   // 32
    for (int kt = 0; kt < NT; kt++) {
        cp_wait0();
        __syncthreads();                       // tile kt landed; prev compute done
        if (kt + 1 < NT) issue_kv(kt + 1, (kt + 1) & 1);

        float* Kb = Ks + (kt & 1) * K_BUF;
        float* Vb = Vs + (kt & 1) * V_BUF;
        cvt_buf(Kb, K_BUF / 4, tid, 256);      // convert ONCE, shared by 8 warps
        cvt_buf(Vb, V_BUF / 4, tid, 256);
        __syncthreads();

        // ---- S = (Q/8) K^T : per warp 16x64, already scaled
        float s[8][4];
        #pragma unroll
        for (int nt = 0; nt < 8; nt++)
            #pragma unroll
            for (int e = 0; e < 4; e++) s[nt][e] = 0.f;
        #pragma unroll
        for (int nt = 0; nt < 8; nt++) {
            const int n0 = nt * 8;
            #pragma unroll
            for (int kk = 0; kk < 8; kk++) {
                const int k0 = kk * 8;
                uint32_t bf[2];
                bf[0] = __float_as_uint(Kb[(n0 + g) * KSTR + k0 + t]);
                bf[1] = __float_as_uint(Kb[(n0 + g) * KSTR + k0 + t + 4]);
                mma_tf32(s[nt], qf[kk], bf);
            }
        }

        // ---- online softmax (row g -> s[..][0..1], row g+8 -> s[..][2..3])
        float tm0 = -1e30f, tm1 = -1e30f;
        #pragma unroll
        for (int nt = 0; nt < 8; nt++) {
            tm0 = fmaxf(tm0, fmaxf(s[nt][0], s[nt][1]));
            tm1 = fmaxf(tm1, fmaxf(s[nt][2], s[nt][3]));
        }
        tm0 = fmaxf(tm0, __shfl_xor_sync(0xffffffffu, tm0, 1));
        tm0 = fmaxf(tm0, __shfl_xor_sync(0xffffffffu, tm0, 2));
        tm1 = fmaxf(tm1, __shfl_xor_sync(0xffffffffu, tm1, 1));
        tm1 = fmaxf(tm1, __shfl_xor_sync(0xffffffffu, tm1, 2));

        const float nm0 = fmaxf(m0, tm0), nm1 = fmaxf(m1, tm1);
        const float c0 = fast_exp(m0 - nm0), c1 = fast_exp(m1 - nm1);
        float rs0 = 0.f, rs1 = 0.f;
        #pragma unroll
        for (int nt = 0; nt < 8; nt++) {
            float p0 = fast_exp(s[nt][0] - nm0);
            float p1 = fast_exp(s[nt][1] - nm0);
            float p2 = fast_exp(s[nt][2] - nm1);
            float p3 = fast_exp(s[nt][3] - nm1);
            rs0 += p0 + p1; rs1 += p2 + p3;
            const int cc = nt * 8 + 2 * t;
            *(float2*)&Ps[(q0 + g) * PSTR + cc] = make_float2(
                __uint_as_float(f2tf32(p0)), __uint_as_float(f2tf32(p1)));
            *(float2*)&Ps[(q0 + g + 8) * PSTR + cc] = make_float2(
                __uint_as_float(f2tf32(p2)), __uint_as_float(f2tf32(p3)));
        }
        rs0 += __shfl_xor_sync(0xffffffffu, rs0, 1);
        rs0 += __shfl_xor_sync(0xffffffffu, rs0, 2);
        rs1 += __shfl_xor_sync(0xffffffffu, rs1, 1);
        rs1 += __shfl_xor_sync(0xffffffffu, rs1, 2);
        m0 = nm0; m1 = nm1;
        l0 = l0 * c0 + rs0;
        l1 = l1 * c1 + rs1;
        #pragma unroll
        for (int dt = 0; dt < 8; dt++) {
            o[dt][0] *= c0; o[dt][1] *= c0;
            o[dt][2] *= c1; o[dt][3] *= c1;
        }
        __syncwarp();   // P rows are per-warp private: warp-level sync suffices

        // ---- O += P V : A-fragments of P from smem (already tf32 bits)
        uint32_t pf[8][4];
        #pragma unroll
        for (int kk = 0; kk < 8; kk++) {
            const int k0 = kk * 8;
            pf[kk][0] = __float_as_uint(Ps[(q0 + g)     * PSTR + k0 + t]);
            pf[kk][1] = __float_as_uint(Ps[(q0 + g + 8) * PSTR + k0 + t]);
            pf[kk][2] = __float_as_uint(Ps[(q0 + g)     * PSTR + k0 + t + 4]);
            pf[kk][3] = __float_as_uint(Ps[(q0 + g + 8) * PSTR + k0 + t + 4]);
        }
        #pragma unroll
        for (int dt = 0; dt < 8; dt++) {
            const int n0 = dt * 8;
            #pragma unroll
            for (int kk = 0; kk < 8; kk++) {
                const int k0 = kk * 8;
                uint32_t bf[2];
                bf[0] = __float_as_uint(Vb[(k0 + t)     * VSTR + n0 + g]);
                bf[1] = __float_as_uint(Vb[(k0 + t + 4) * VSTR + n0 + g]);
                mma_tf32(o[dt], pf[kk], bf);
            }
        }
        __syncthreads();   // all warps done with Kb/Vb before buffer reuse
    }

    // ---- epilogue: normalize, write ctx in [B,S,H*Dh] layout
    const float inv0 = 1.0f / l0, inv1 = 1.0f / l1;
    float* Cg = g_CTX + ((size_t)(b * N_SEQ + s0 + q0)) * D_MODEL + h * D_HEAD;
    #pragma unroll
    for (int dt = 0; dt < 8; dt++) {
        const int cc = dt * 8 + 2 * t;
        *(float2*)(Cg + (size_t)g * D_MODEL + cc) =
            make_float2(o[dt][0] * inv0, o[dt][1] * inv0);
        *(float2*)(Cg + (size_t)(g + 8) * D_MODEL + cc) =
            make_float2(o[dt][2] * inv1, o[dt][3] * inv1);
    }
}

// ---------------------------------------------------------------------------
extern "C" void kernel_launch(void* const* d_in, const int* in_sizes, int n_in,
                              void* d_out, int out_size)
{
    (void)in_sizes; (void)n_in; (void)out_size;
    const float* q  = (const float*)d_in[0];
    const float* k  = (const float*)d_in[1];
    const float* v  = (const float*)d_in[2];
    const float* Wq = (const float*)d_in[3];
    const float* bq = (const float*)d_in[4];
    const float* Wk = (const float*)d_in[5];
    const float* bk = (const float*)d_in[6];
    const float* Wv = (const float*)d_in[7];
    const float* bv = (const float*)d_in[8];
    const float* Wo = (const float*)d_in[9];
    const float* bo = (const float*)d_in[10];
    float* out = (float*)d_out;

    float *Qd, *Kd, *Vd, *Cd;
    cudaGetSymbolAddress((void**)&Qd, g_Q);
    cudaGetSymbolAddress((void**)&Kd, g_K);
    cudaGetSymbolAddress((void**)&Vd, g_V);
    cudaGetSymbolAddress((void**)&Cd, g_CTX);

    cudaFuncSetAttribute(gemm_bias_kernel,
                         cudaFuncAttributeMaxDynamicSharedMemorySize, GEMM_SMEM);
    cudaFuncSetAttribute(attn_kernel,
                         cudaFuncAttributeMaxDynamicSharedMemorySize, ATTN_SMEM);

    dim3 ggrid(D_MODEL / BN, N_ROWS / BM);   // (8, 64)
    gemm_bias_kernel<<<ggrid, 256, GEMM_SMEM>>>(q, Wq, bq, Qd);
    gemm_bias_kernel<<<ggrid, 256, GEMM_SMEM>>>(k, Wk, bk, Kd);
    gemm_bias_kernel<<<ggrid, 256, GEMM_SMEM>>>(v, Wv, bv, Vd);
    attn_kernel<<<dim3(N_SEQ / QTILE, N_HEADS, N_BATCH), 256, ATTN_SMEM>>>();
    gemm_bias_kernel<<<ggrid, 256, GEMM_SMEM>>>(Cd, Wo, bo, out);
}

// round 3
// speedup vs baseline: 1.2408x; 1.2408x over previous
#include <cuda_runtime.h>
#include <cstdint>
#include <cstddef>

#define D_MODEL 1024
#define N_BATCH 4
#define N_SEQ   2048
#define N_HEADS 16
#define D_HEAD  64
#define N_ROWS  (N_BATCH * N_SEQ)   // 8192

// Scratch (device-global: no allocations allowed in kernel_launch).
__device__ float g_Q[(size_t)N_ROWS * D_MODEL];
__device__ float g_K[(size_t)N_ROWS * D_MODEL];
__device__ float g_V[(size_t)N_ROWS * D_MODEL];
__device__ float g_CTX[(size_t)N_ROWS * D_MODEL];
// tf32-pre-rounded copies of inputs / weights
__device__ float g_qc[(size_t)N_ROWS * D_MODEL];
__device__ float g_kc[(size_t)N_ROWS * D_MODEL];
__device__ float g_vc[(size_t)N_ROWS * D_MODEL];
__device__ float g_Wqc[(size_t)D_MODEL * D_MODEL];
__device__ float g_Wkc[(size_t)D_MODEL * D_MODEL];
__device__ float g_Wvc[(size_t)D_MODEL * D_MODEL];
__device__ float g_Woc[(size_t)D_MODEL * D_MODEL];

// ---------------------------------------------------------------------------
// Helpers
// ---------------------------------------------------------------------------
__device__ __forceinline__ uint32_t f2tf32(float x) {
    uint32_t r;
    asm("cvt.rna.tf32.f32 %0, %1;" : "=r"(r) : "f"(x));
    return r;
}

// D += A(16x8,row) * B(8x8,col)  tf32 -> fp32
__device__ __forceinline__ void mma_tf32(float d[4], const uint32_t a[4], const uint32_t b[2]) {
    asm volatile(
        "mma.sync.aligned.m16n8k8.row.col.f32.tf32.tf32.f32 "
        "{%0,%1,%2,%3}, {%4,%5,%6,%7}, {%8,%9}, {%0,%1,%2,%3};\n"
        : "+f"(d[0]), "+f"(d[1]), "+f"(d[2]), "+f"(d[3])
        : "r"(a[0]), "r"(a[1]), "r"(a[2]), "r"(a[3]), "r"(b[0]), "r"(b[1]));
}

__device__ __forceinline__ void cp16(uint32_t s, const void* g) {
    asm volatile("cp.async.cg.shared.global [%0], [%1], 16;\n" :: "r"(s), "l"(g));
}
__device__ __forceinline__ void cp_commit() { asm volatile("cp.async.commit_group;\n"); }
__device__ __forceinline__ void cp_wait0()  { asm volatile("cp.async.wait_group 0;\n"); }

// exp(x) for x <= 0 using only FMA/ALU pipe. ~3e-6 rel accuracy.
__device__ __forceinline__ float fast_exp(float x) {
    float t = fmaxf(x * 1.4426950408889634f, -126.0f);
    float z = t + 12582912.0f;
    int  ki = __float_as_int(z) - 0x4B400000;
    float f = t - (z - 12582912.0f);
    float u = f * 0.6931471805599453f;
    float p = 1.0f + u * (1.0f + u * (0.5f + u * (0.16666667f +
              u * (0.041666668f + u * 0.008333334f))));
    return __int_as_float(__float_as_int(p) + (ki << 23));
}

// ---------------------------------------------------------------------------
// Elementwise tf32 pre-round: out[i] = round_tf32(in[i]), float4-vectorized.
// One pass over gmem; removes ALL per-tile conversion from the hot kernels.
// ---------------------------------------------------------------------------
__global__ void __launch_bounds__(256)
cvt_tf32_kernel(const float4* __restrict__ in, float4* __restrict__ out, int n4)
{
    for (int i = blockIdx.x * blockDim.x + threadIdx.x; i < n4;
         i += gridDim.x * blockDim.x) {
        float4 v = in[i];
        v.x = __uint_as_float(f2tf32(v.x));
        v.y = __uint_as_float(f2tf32(v.y));
        v.z = __uint_as_float(f2tf32(v.z));
        v.w = __uint_as_float(f2tf32(v.w));
        out[i] = v;
    }
}

// ---------------------------------------------------------------------------
// GEMM: C[8192,1024] = A[8192,1024] @ W[1024,1024] + bias
// Operands are PRE-ROUNDED tf32 bit patterns -> mainloop is pure LDS + HMMA.
// BM=128 BN=128 BK=32, 256 threads (8 warps 4x2), warp tile 32x64,
// cp.async double-buffered, single barrier per k-tile.
// blockIdx.z selects one of up to 3 (A,W,bias,C) sets (fused QKV launch).
// round_out: epilogue writes tf32-pre-rounded values (for Q/K/V scratch).
// ---------------------------------------------------------------------------
#define BM 128
#define BN 128
#define BK 32
#define ASTR 36    // (36g+t)%32 = 4g+t -> conflict-free A-frag LDS
#define BSTR 136   // (136t+g)%32 = 8t+g -> conflict-free B-frag LDS
#define A_BUF (BM * ASTR)            // 4608 floats
#define B_BUF (BK * BSTR)            // 4352 floats
#define GEMM_SMEM ((2 * A_BUF + 2 * B_BUF) * 4)   // 71680 B

struct GemmSet { const float* A; const float* W; const float* bias; float* C; };

__global__ void __launch_bounds__(256)
gemm_bias_kernel(GemmSet s0, GemmSet s1, GemmSet s2, int round_out)
{
    const GemmSet& S = (blockIdx.z == 0) ? s0 : (blockIdx.z == 1) ? s1 : s2;
    const float* __restrict__ A    = S.A;
    const float* __restrict__ W    = S.W;
    const float* __restrict__ bias = S.bias;
    float* __restrict__ C          = S.C;

    extern __shared__ float smem[];
    float* As = smem;                     // [2][BM][ASTR]
    float* Bs = smem + 2 * A_BUF;         // [2][BK][BSTR]
    const uint32_t sA = (uint32_t)__cvta_generic_to_shared(As);
    const uint32_t sB = (uint32_t)__cvta_generic_to_shared(Bs);

    const int tid  = threadIdx.x;
    const int warp = tid >> 5, lane = tid & 31;
    const int g = lane >> 2, t = lane & 3;
    const int wm = warp >> 1, wn = warp & 1;
    const int m_base = wm * 32, n_base = wn * 64;
    const int cta_m = blockIdx.y * BM;
    const int cta_n = blockIdx.x * BN;

    float acc[2][8][4];
    #pragma unroll
    for (int i = 0; i < 2; i++)
        #pragma unroll
        for (int j = 0; j < 8; j++)
            #pragma unroll
            for (int e = 0; e < 4; e++) acc[i][j][e] = 0.f;

    auto issue_loads = [&](int kt, int buf) {
        const float* Ag = A + (size_t)cta_m * D_MODEL + kt * BK;
        #pragma unroll
        for (int i = 0; i < 4; i++) {
            int idx = tid + i * 256;
            int r = idx >> 3, c = (idx & 7) * 4;
            cp16(sA + (uint32_t)(buf * A_BUF + r * ASTR + c) * 4,
                 Ag + (size_t)r * D_MODEL + c);
        }
        const float* Wg = W + (size_t)(kt * BK) * D_MODEL + cta_n;
        #pragma unroll
        for (int i = 0; i < 4; i++) {
            int idx = tid + i * 256;
            int r = idx >> 5, c = (idx & 31) * 4;
            cp16(sB + (uint32_t)(buf * B_BUF + r * BSTR + c) * 4,
                 Wg + (size_t)r * D_MODEL + c);
        }
        cp_commit();
    };

    issue_loads(0, 0);

    const int KT = D_MODEL / BK;  // 32
    for (int kt = 0; kt < KT; kt++) {
        cp_wait0();
        __syncthreads();   // tile kt landed AND everyone done with buffer (kt+1)&1
        if (kt + 1 < KT) issue_loads(kt + 1, (kt + 1) & 1);

        const float* Ab = As + (kt & 1) * A_BUF;
        const float* Bb = Bs + (kt & 1) * B_BUF;
        #pragma unroll
        for (int kk = 0; kk < 4; kk++) {
            const int k0 = kk * 8;
            uint32_t af[2][4], bf[8][2];
            #pragma unroll
            for (int mt = 0; mt < 2; mt++) {
                const int m0 = m_base + mt * 16;
                af[mt][0] = __float_as_uint(Ab[(m0 + g)     * ASTR + k0 + t]);
                af[mt][1] = __float_as_uint(Ab[(m0 + g + 8) * ASTR + k0 + t]);
                af[mt][2] = __float_as_uint(Ab[(m0 + g)     * ASTR + k0 + t + 4]);
                af[mt][3] = __float_as_uint(Ab[(m0 + g + 8) * ASTR + k0 + t + 4]);
            }
            #pragma unroll
            for (int nt = 0; nt < 8; nt++) {
                const int n0 = n_base + nt * 8;
                bf[nt][0] = __float_as_uint(Bb[(k0 + t)     * BSTR + n0 + g]);
                bf[nt][1] = __float_as_uint(Bb[(k0 + t + 4) * BSTR + n0 + g]);
            }
            #pragma unroll
            for (int mt = 0; mt < 2; mt++)
                #pragma unroll
                for (int nt = 0; nt < 8; nt++)
                    mma_tf32(acc[mt][nt], af[mt], bf[nt]);
        }
    }

    // Epilogue: + bias; optionally pre-round to tf32 for downstream consumers.
    #pragma unroll
    for (int mt = 0; mt < 2; mt++) {
        #pragma unroll
        for (int nt = 0; nt < 8; nt++) {
            int r0 = cta_m + m_base + mt * 16 + g;
            int c0 = cta_n + n_base + nt * 8 + 2 * t;
            float b0 = bias[c0], b1 = bias[c0 + 1];
            float v00 = acc[mt][nt][0] + b0, v01 = acc[mt][nt][1] + b1;
            float v10 = acc[mt][nt][2] + b0, v11 = acc[mt][nt][3] + b1;
            if (round_out) {
                v00 = __uint_as_float(f2tf32(v00));
                v01 = __uint_as_float(f2tf32(v01));
                v10 = __uint_as_float(f2tf32(v10));
                v11 = __uint_as_float(f2tf32(v11));
            }
            *(float2*)(C + (size_t)r0 * D_MODEL + c0)       = make_float2(v00, v01);
            *(float2*)(C + (size_t)(r0 + 8) * D_MODEL + c0) = make_float2(v10, v11);
        }
    }
}

// ---------------------------------------------------------------------------
// Flash attention: one CTA = 128 queries of one (b,h). 8 warps, each owns 16
// query rows (softmax warp-local). K/V tiles double-buffered; operands arrive
// PRE-ROUNDED tf32 from the projection GEMMs -> zero conversion in mainloop.
// ---------------------------------------------------------------------------
#define QTILE 128
#define KSTR 68   // (68g+t)%32 = 4g+t -> conflict-free B-frag reads of K
#define VSTR 72   // (72t+g)%32 = 8t+g -> conflict-free B-frag reads of V
#define PSTR 68
#define K_BUF (64 * KSTR)   // 4352 floats
#define V_BUF (64 * VSTR)   // 4608 floats
#define ATTN_SMEM ((2 * K_BUF + 2 * V_BUF + QTILE * PSTR) * 4)   // 106496 B

__global__ void __launch_bounds__(256)
attn_kernel()
{
    extern __shared__ float sm[];
    float* Ks = sm;                         // [2][64][KSTR]
    float* Vs = sm + 2 * K_BUF;             // [2][64][VSTR]
    float* Ps = sm + 2 * K_BUF + 2 * V_BUF; // [128][PSTR] Q staging then P
    const uint32_t sK = (uint32_t)__cvta_generic_to_shared(Ks);
    const uint32_t sV = (uint32_t)__cvta_generic_to_shared(Vs);
    const uint32_t sP = (uint32_t)__cvta_generic_to_shared(Ps);

    const int tid  = threadIdx.x;
    const int warp = tid >> 5, lane = tid & 31;
    const int g = lane >> 2, t = lane & 3;
    const int b = blockIdx.z, h = blockIdx.y;
    const int s0 = blockIdx.x * QTILE;
    const int q0 = warp * 16;

    // ---- stage Q tile, pull A-fragments (x0.125 is exact on tf32 grid)
    {
        const float* Qg = g_Q + ((size_t)(b * N_SEQ + s0)) * D_MODEL + h * D_HEAD;
        #pragma unroll
        for (int i = 0; i < 8; i++) {
            int idx = tid + i * 256;
            int r = idx >> 4, c = (idx & 15) * 4;
            cp16(sP + (uint32_t)(r * PSTR + c) * 4, Qg + (size_t)r * D_MODEL + c);
        }
        cp_commit(); cp_wait0();
        __syncthreads();
    }
    uint32_t qf[8][4];
    #pragma unroll
    for (int kk = 0; kk < 8; kk++) {
        const int k0 = kk * 8;
        qf[kk][0] = __float_as_uint(Ps[(q0 + g)     * PSTR + k0 + t]     * 0.125f);
        qf[kk][1] = __float_as_uint(Ps[(q0 + g + 8) * PSTR + k0 + t]     * 0.125f);
        qf[kk][2] = __float_as_uint(Ps[(q0 + g)     * PSTR + k0 + t + 4] * 0.125f);
        qf[kk][3] = __float_as_uint(Ps[(q0 + g + 8) * PSTR + k0 + t + 4] * 0.125f);
    }
    __syncthreads();   // Ps now reusable as P buffer

    auto issue_kv = [&](int kt, int buf) {
        const float* Kg = g_K + ((size_t)(b * N_SEQ + kt * 64)) * D_MODEL + h * D_HEAD;
        const float* Vg = g_V + ((size_t)(b * N_SEQ + kt * 64)) * D_MODEL + h * D_HEAD;
        #pragma unroll
        for (int i = 0; i < 4; i++) {
            int idx = tid + i * 256;
            int r = idx >> 4, c = (idx & 15) * 4;
            cp16(sK + (uint32_t)(buf * K_BUF + r * KSTR + c) * 4,
                 Kg + (size_t)r * D_MODEL + c);
            cp16(sV + (uint32_t)(buf * V_BUF + r * VSTR + c) * 4,
                 Vg + (size_t)r * D_MODEL + c);
        }
        cp_commit();
    };

    float m0 = -1e30f, m1 = -1e30f, l0 = 0.f, l1 = 0.f;
    float o[8][4];
    #pragma unroll
    for (int dt = 0; dt < 8; dt++)
        #pragma unroll
        for (int e = 0; e < 4; e++) o[dt][e] = 0.f;

    issue_kv(0, 0);

    const int NT = N_SEQ / 64;   // 32
    for (int kt = 0; kt < NT; kt++) {
        cp_wait0();
        __syncthreads();   // tile kt landed AND all warps done with other buffer
        if (kt + 1 < NT) issue_kv(kt + 1, (kt + 1) & 1);

        const float* Kb = Ks + (kt & 1) * K_BUF;
        const float* Vb = Vs + (kt & 1) * V_BUF;

        // ---- S = (Q/8) K^T : per warp 16x64
        float s[8][4];
        #pragma unroll
        for (int nt = 0; nt < 8; nt++)
            #pragma unroll
            for (int e = 0; e < 4; e++) s[nt][e] = 0.f;
        #pragma unroll
        for (int nt = 0; nt < 8; nt++) {
            const int n0 = nt * 8;
            #pragma unroll
            for (int kk = 0; kk < 8; kk++) {
                const int k0 = kk * 8;
                uint32_t bf[2];
                bf[0] = __float_as_uint(Kb[(n0 + g) * KSTR + k0 + t]);
                bf[1] = __float_as_uint(Kb[(n0 + g) * KSTR + k0 + t + 4]);
                mma_tf32(s[nt], qf[kk], bf);
            }
        }

        // ---- online softmax (row g -> s[..][0..1], row g+8 -> s[..][2..3])
        float tm0 = -1e30f, tm1 = -1e30f;
        #pragma unroll
        for (int nt = 0; nt < 8; nt++) {
            tm0 = fmaxf(tm0, fmaxf(s[nt][0], s[nt][1]));
            tm1 = fmaxf(tm1, fmaxf(s[nt][2], s[nt][3]));
        }
        tm0 = fmaxf(tm0, __shfl_xor_sync(0xffffffffu, tm0, 1));
        tm0 = fmaxf(tm0, __shfl_xor_sync(0xffffffffu, tm0, 2));
        tm1 = fmaxf(tm1, __shfl_xor_sync(0xffffffffu, tm1, 1));
        tm1 = fmaxf(tm1, __shfl_xor_sync(0xffffffffu, tm1, 2));

        const float nm0 = fmaxf(m0, tm0), nm1 = fmaxf(m1, tm1);
        const float c0 = fast_exp(m0 - nm0), c1 = fast_exp(m1 - nm1);
        float rs0 = 0.f, rs1 = 0.f;
        #pragma unroll
        for (int nt = 0; nt < 8; nt++) {
            float p0 = fast_exp(s[nt][0] - nm0);
            float p1 = fast_exp(s[nt][1] - nm0);
            float p2 = fast_exp(s[nt][2] - nm1);
            float p3 = fast_exp(s[nt][3] - nm1);
            rs0 += p0 + p1; rs1 += p2 + p3;
            const int cc = nt * 8 + 2 * t;
            *(float2*)&Ps[(q0 + g) * PSTR + cc] = make_float2(
                __uint_as_float(f2tf32(p0)), __uint_as_float(f2tf32(p1)));
            *(float2*)&Ps[(q0 + g + 8) * PSTR + cc] = make_float2(
                __uint_as_float(f2tf32(p2)), __uint_as_float(f2tf32(p3)));
        }
        rs0 += __shfl_xor_sync(0xffffffffu, rs0, 1);
        rs0 += __shfl_xor_sync(0xffffffffu, rs0, 2);
        rs1 += __shfl_xor_sync(0xffffffffu, rs1, 1);
        rs1 += __shfl_xor_sync(0xffffffffu, rs1, 2);
        m0 = nm0; m1 = nm1;
        l0 = l0 * c0 + rs0;
        l1 = l1 * c1 + rs1;
        #pragma unroll
        for (int dt = 0; dt < 8; dt++) {
            o[dt][0] *= c0; o[dt][1] *= c0;
            o[dt][2] *= c1; o[dt][3] *= c1;
        }
        __syncwarp();   // P rows are per-warp private

        // ---- O += P V
        uint32_t pf[8][4];
        #pragma unroll
        for (int kk = 0; kk < 8; kk++) {
            const int k0 = kk * 8;
            pf[kk][0] = __float_as_uint(Ps[(q0 + g)     * PSTR + k0 + t]);
            pf[kk][1] = __float_as_uint(Ps[(q0 + g + 8) * PSTR + k0 + t]);
            pf[kk][2] = __float_as_uint(Ps[(q0 + g)     * PSTR + k0 + t + 4]);
            pf[kk][3] = __float_as_uint(Ps[(q0 + g + 8) * PSTR + k0 + t + 4]);
        }
        #pragma unroll
        for (int dt = 0; dt < 8; dt++) {
            const int n0 = dt * 8;
            #pragma unroll
            for (int kk = 0; kk < 8; kk++) {
                const int k0 = kk * 8;
                uint32_t bf[2];
                bf[0] = __float_as_uint(Vb[(k0 + t)     * VSTR + n0 + g]);
                bf[1] = __float_as_uint(Vb[(k0 + t + 4) * VSTR + n0 + g]);
                mma_tf32(o[dt], pf[kk], bf);
            }
        }
    }

    // ---- epilogue: normalize, pre-round, write ctx in [B,S,H*Dh] layout
    const float inv0 = 1.0f / l0, inv1 = 1.0f / l1;
    float* Cg = g_CTX + ((size_t)(b * N_SEQ + s0 + q0)) * D_MODEL + h * D_HEAD;
    #pragma unroll
    for (int dt = 0; dt < 8; dt++) {
        const int cc = dt * 8 + 2 * t;
        *(float2*)(Cg + (size_t)g * D_MODEL + cc) = make_float2(
            __uint_as_float(f2tf32(o[dt][0] * inv0)),
            __uint_as_float(f2tf32(o[dt][1] * inv0)));
        *(float2*)(Cg + (size_t)(g + 8) * D_MODEL + cc) = make_float2(
            __uint_as_float(f2tf32(o[dt][2] * inv1)),
            __uint_as_float(f2tf32(o[dt][3] * inv1)));
    }
}

// ---------------------------------------------------------------------------
extern "C" void kernel_launch(void* const* d_in, const int* in_sizes, int n_in,
                              void* d_out, int out_size)
{
    (void)in_sizes; (void)n_in; (void)out_size;
    const float* q  = (const float*)d_in[0];
    const float* k  = (const float*)d_in[1];
    const float* v  = (const float*)d_in[2];
    const float* Wq = (const float*)d_in[3];
    const float* bq = (const float*)d_in[4];
    const float* Wk = (const float*)d_in[5];
    const float* bk = (const float*)d_in[6];
    const float* Wv = (const float*)d_in[7];
    const float* bv = (const float*)d_in[8];
    const float* Wo = (const float*)d_in[9];
    const float* bo = (const float*)d_in[10];
    float* out = (float*)d_out;

    float *Qd, *Kd, *Vd, *Cd, *qc, *kc, *vc, *Wqc, *Wkc, *Wvc, *Woc;
    cudaGetSymbolAddress((void**)&Qd,  g_Q);
    cudaGetSymbolAddress((void**)&Kd,  g_K);
    cudaGetSymbolAddress((void**)&Vd,  g_V);
    cudaGetSymbolAddress((void**)&Cd,  g_CTX);
    cudaGetSymbolAddress((void**)&qc,  g_qc);
    cudaGetSymbolAddress((void**)&kc,  g_kc);
    cudaGetSymbolAddress((void**)&vc,  g_vc);
    cudaGetSymbolAddress((void**)&Wqc, g_Wqc);
    cudaGetSymbolAddress((void**)&Wkc, g_Wkc);
    cudaGetSymbolAddress((void**)&Wvc, g_Wvc);
    cudaGetSymbolAddress((void**)&Woc, g_Woc);

    cudaFuncSetAttribute(gemm_bias_kernel,
                         cudaFuncAttributeMaxDynamicSharedMemorySize, GEMM_SMEM);
    cudaFuncSetAttribute(attn_kernel,
                         cudaFuncAttributeMaxDynamicSharedMemorySize, ATTN_SMEM);

    const int N4_IN = N_ROWS * D_MODEL / 4;   // 2M float4
    const int N4_W  = D_MODEL * D_MODEL / 4;  // 256K float4
    cvt_tf32_kernel<<<1184, 256>>>((const float4*)q,  (float4*)qc,  N4_IN);
    cvt_tf32_kernel<<<1184, 256>>>((const float4*)k,  (float4*)kc,  N4_IN);
    cvt_tf32_kernel<<<1184, 256>>>((const float4*)v,  (float4*)vc,  N4_IN);
    cvt_tf32_kernel<<<592, 256>>>((const float4*)Wq, (float4*)Wqc, N4_W);
    cvt_tf32_kernel<<<592, 256>>>((const float4*)Wk, (float4*)Wkc, N4_W);
    cvt_tf32_kernel<<<592, 256>>>((const float4*)Wv, (float4*)Wvc, N4_W);
    cvt_tf32_kernel<<<592, 256>>>((const float4*)Wo, (float4*)Woc, N4_W);

    GemmSet sq{qc, Wqc, bq, Qd};
    GemmSet sk{kc, Wkc, bk, Kd};
    GemmSet sv{vc, Wvc, bv, Vd};
    // Fused QKV projection: blockIdx.z in {0,1,2}
    dim3 qkv_grid(D_MODEL / BN, N_ROWS / BM, 3);   // (8, 64, 3)
    gemm_bias_kernel<<<qkv_grid, 256, GEMM_SMEM>>>(sq, sk, sv, 1);

    attn_kernel<<<dim3(N_SEQ / QTILE, N_HEADS, N_BATCH), 256, ATTN_SMEM>>>();

    GemmSet so{Cd, Woc, bo, out};
    gemm_bias_kernel<<<dim3(D_MODEL / BN, N_ROWS / BM, 1), 256, GEMM_SMEM>>>(
        so, so, so, 0);
}